// round 1
// baseline (speedup 1.0000x reference)
#include <cuda_runtime.h>
#include <cuda_bf16.h>
#include <cstdint>

// Problem constants
#define NT 2048      // tokens
#define NE 8         // experts
#define DM 1024      // d_model
#define DF 4096      // d_ff
#define TOPK 2
#define NA (NT*TOPK) // 4096 assignments

// ---------------- scratch (device globals: no allocations allowed) ----------
__device__ int   g_cnt[NE];
__device__ int   g_tok[NE * NA];   // token id per slot
__device__ int   g_asg[NE * NA];   // assignment id per slot
__device__ float g_hidden[(size_t)NA * DF];  // 64 MB
__device__ float g_obuf[(size_t)NA * DM];    // 16 MB

// ---------------- routing ---------------------------------------------------
__global__ void reset_counts_k() {
    if (threadIdx.x < NE) g_cnt[threadIdx.x] = 0;
}

__global__ void route_k(const int* __restrict__ idx) {
    int a = blockIdx.x * blockDim.x + threadIdx.x;
    if (a >= NA) return;
    int e = idx[a];
    int p = atomicAdd(&g_cnt[e], 1);
    g_tok[e * NA + p] = a >> 1;   // token id
    g_asg[e * NA + p] = a;        // assignment id
}

// ---------------- fused up-projection: gate=silu(X W1), val=X W2, h=gate*val
// Tiled GEMM: BM=64, BN=64, BK=16, 256 threads, 4x4 micro-tile per thread,
// both GEMMs share the X tile.
__global__ __launch_bounds__(256) void up_k(const float* __restrict__ x,
                                            const float* __restrict__ w1,
                                            const float* __restrict__ w2) {
    const int e   = blockIdx.z;
    const int cnt = g_cnt[e];
    const int m0  = blockIdx.y * 64;
    if (m0 >= cnt) return;
    const int n0  = blockIdx.x * 64;

    __shared__ float sX[16][65];   // [k][m], padded
    __shared__ float sW1[16][64];  // [k][n]
    __shared__ float sW2[16][64];

    const int tid = threadIdx.x;
    const int tx  = tid & 15;   // n
    const int ty  = tid >> 4;   // m

    float acc1[4][4]; float acc2[4][4];
    #pragma unroll
    for (int i = 0; i < 4; i++)
        #pragma unroll
        for (int j = 0; j < 4; j++) { acc1[i][j] = 0.f; acc2[i][j] = 0.f; }

    // X-tile load mapping: 64 rows x 16 cols = 256 float4
    const int lr = tid >> 2;          // row in tile 0..63
    const int lc = (tid & 3) * 4;     // col 0,4,8,12
    const int gm = m0 + lr;
    const float* xrow = (gm < cnt) ? (x + (size_t)g_tok[e * NA + gm] * DM) : nullptr;

    // W-tile load mapping: 16 rows x 64 cols = 256 float4
    const int wr = tid >> 4;          // k row 0..15
    const int wc = (tid & 15) * 4;    // n col
    const float* w1p = w1 + (size_t)e * DM * DF + n0;
    const float* w2p = w2 + (size_t)e * DM * DF + n0;

    for (int k0 = 0; k0 < DM; k0 += 16) {
        float4 xv = make_float4(0.f, 0.f, 0.f, 0.f);
        if (xrow) xv = *(const float4*)(xrow + k0 + lc);
        sX[lc + 0][lr] = xv.x;
        sX[lc + 1][lr] = xv.y;
        sX[lc + 2][lr] = xv.z;
        sX[lc + 3][lr] = xv.w;
        *(float4*)&sW1[wr][wc] = *(const float4*)(w1p + (size_t)(k0 + wr) * DF + wc);
        *(float4*)&sW2[wr][wc] = *(const float4*)(w2p + (size_t)(k0 + wr) * DF + wc);
        __syncthreads();

        #pragma unroll
        for (int k = 0; k < 16; k++) {
            float xa[4];
            #pragma unroll
            for (int i = 0; i < 4; i++) xa[i] = sX[k][ty * 4 + i];
            float4 b1 = *(float4*)&sW1[k][tx * 4];
            float4 b2 = *(float4*)&sW2[k][tx * 4];
            float wa1[4] = {b1.x, b1.y, b1.z, b1.w};
            float wa2[4] = {b2.x, b2.y, b2.z, b2.w};
            #pragma unroll
            for (int i = 0; i < 4; i++)
                #pragma unroll
                for (int j = 0; j < 4; j++) {
                    acc1[i][j] = fmaf(xa[i], wa1[j], acc1[i][j]);
                    acc2[i][j] = fmaf(xa[i], wa2[j], acc2[i][j]);
                }
        }
        __syncthreads();
    }

    // epilogue: hidden[a][n] = silu(gate) * value
    #pragma unroll
    for (int i = 0; i < 4; i++) {
        int m = m0 + ty * 4 + i;
        if (m >= cnt) break;
        int a = g_asg[e * NA + m];
        float* hrow = g_hidden + (size_t)a * DF + n0 + tx * 4;
        float4 r;
        float g, v;
        g = acc1[i][0]; v = acc2[i][0]; r.x = (g / (1.f + expf(-g))) * v;
        g = acc1[i][1]; v = acc2[i][1]; r.y = (g / (1.f + expf(-g))) * v;
        g = acc1[i][2]; v = acc2[i][2]; r.z = (g / (1.f + expf(-g))) * v;
        g = acc1[i][3]; v = acc2[i][3]; r.w = (g / (1.f + expf(-g))) * v;
        *(float4*)hrow = r;
    }
}

// ---------------- down-projection: obuf[a] = (hidden[a] @ W3[e]) * gate_w[a]
__global__ __launch_bounds__(256) void down_k(const float* __restrict__ w3,
                                              const float* __restrict__ ew) {
    const int e   = blockIdx.z;
    const int cnt = g_cnt[e];
    const int m0  = blockIdx.y * 64;
    if (m0 >= cnt) return;
    const int n0  = blockIdx.x * 64;

    __shared__ float sH[16][65];
    __shared__ float sW[16][64];

    const int tid = threadIdx.x;
    const int tx  = tid & 15;
    const int ty  = tid >> 4;

    float acc[4][4];
    #pragma unroll
    for (int i = 0; i < 4; i++)
        #pragma unroll
        for (int j = 0; j < 4; j++) acc[i][j] = 0.f;

    const int lr = tid >> 2;
    const int lc = (tid & 3) * 4;
    const int gm = m0 + lr;
    const float* hrow = (gm < cnt) ? (g_hidden + (size_t)g_asg[e * NA + gm] * DF) : nullptr;

    const int wr = tid >> 4;
    const int wc = (tid & 15) * 4;
    const float* w3p = w3 + (size_t)e * DF * DM + n0;

    for (int k0 = 0; k0 < DF; k0 += 16) {
        float4 hv = make_float4(0.f, 0.f, 0.f, 0.f);
        if (hrow) hv = *(const float4*)(hrow + k0 + lc);
        sH[lc + 0][lr] = hv.x;
        sH[lc + 1][lr] = hv.y;
        sH[lc + 2][lr] = hv.z;
        sH[lc + 3][lr] = hv.w;
        *(float4*)&sW[wr][wc] = *(const float4*)(w3p + (size_t)(k0 + wr) * DM + wc);
        __syncthreads();

        #pragma unroll
        for (int k = 0; k < 16; k++) {
            float ha[4];
            #pragma unroll
            for (int i = 0; i < 4; i++) ha[i] = sH[k][ty * 4 + i];
            float4 b = *(float4*)&sW[k][tx * 4];
            float wa[4] = {b.x, b.y, b.z, b.w};
            #pragma unroll
            for (int i = 0; i < 4; i++)
                #pragma unroll
                for (int j = 0; j < 4; j++)
                    acc[i][j] = fmaf(ha[i], wa[j], acc[i][j]);
        }
        __syncthreads();
    }

    #pragma unroll
    for (int i = 0; i < 4; i++) {
        int m = m0 + ty * 4 + i;
        if (m >= cnt) break;
        int a  = g_asg[e * NA + m];
        float s = ew[a];
        float* orow = g_obuf + (size_t)a * DM + n0 + tx * 4;
        float4 r;
        r.x = acc[i][0] * s;
        r.y = acc[i][1] * s;
        r.z = acc[i][2] * s;
        r.w = acc[i][3] * s;
        *(float4*)orow = r;
    }
}

// ---------------- combine: out[t] = obuf[2t] + obuf[2t+1] (deterministic) ----
__global__ void combine_k(float* __restrict__ out) {
    int i = blockIdx.x * blockDim.x + threadIdx.x;   // over NT*DM/4
    const int W = DM / 4;
    if (i >= NT * W) return;
    int t = i / W;
    int c = i - t * W;
    const float4* buf = (const float4*)g_obuf;
    float4 a0 = buf[(size_t)(2 * t) * W + c];
    float4 a1 = buf[(size_t)(2 * t + 1) * W + c];
    float4 r = make_float4(a0.x + a1.x, a0.y + a1.y, a0.z + a1.z, a0.w + a1.w);
    ((float4*)out)[i] = r;
}

// ---------------- launch -----------------------------------------------------
extern "C" void kernel_launch(void* const* d_in, const int* in_sizes, int n_in,
                              void* d_out, int out_size) {
    const float* x   = (const float*)d_in[0];
    const int*   idx = (const int*)d_in[1];
    const float* ew  = (const float*)d_in[2];
    const float* w1  = (const float*)d_in[3];
    const float* w2  = (const float*)d_in[4];
    const float* w3  = (const float*)d_in[5];
    float* out = (float*)d_out;

    reset_counts_k<<<1, 32>>>();
    route_k<<<NA / 256, 256>>>(idx);

    // up: grid (F/64, capacity/64, E)
    up_k<<<dim3(DF / 64, NA / 64, NE), 256>>>(x, w1, w2);
    // down: grid (D/64, capacity/64, E)
    down_k<<<dim3(DM / 64, NA / 64, NE), 256>>>(w3, ew);

    combine_k<<<(NT * (DM / 4) + 255) / 256, 256>>>(out);
}

// round 3
// speedup vs baseline: 2.1586x; 2.1586x over previous
#include <cuda_runtime.h>
#include <cuda_bf16.h>
#include <cstdint>

// ---------------- problem constants -----------------------------------------
#define NT 2048
#define NE 8
#define DM 1024
#define DF 4096
#define TOPK 2
#define NA (NT*TOPK)

// ---------------- tiling -----------------------------------------------------
#define BM 128
#define BK 32
// smem row strides (bf16 elems), padded for conflict-free ldmatrix
#define A_STRIDE 40      // 80 B rows  (pos = 5m + c mod 8 distinct)
#define B_STRIDE 136     // 272 B rows (pos = 17k + c mod 8 distinct)
#define ST_A (BM * A_STRIDE * 2)   // 10240 B
#define ST_B (BK * B_STRIDE * 2)   // 8704 B
#define STAGE (2*ST_A + 2*ST_B)    // 37888 B (A_h, A_l, B_h, B_l)
#define SMEMSZ (2*STAGE)           // 75776 B

// ---------------- device scratch ---------------------------------------------
__device__ int   g_cnt[NE];
__device__ int   g_tok[NE * NA];
__device__ int   g_asg[NE * NA];
__device__ float g_hidden[(size_t)NA * DF];   // 64 MB
__device__ float g_obuf[(size_t)NA * DM];     // 16 MB

// ---------------- helpers ----------------------------------------------------
__device__ __forceinline__ uint32_t smem_u32(const void* p) {
    uint32_t a;
    asm("{ .reg .u64 t; cvta.to.shared.u64 t, %1; cvt.u32.u64 %0, t; }" : "=r"(a) : "l"(p));
    return a;
}

__device__ __forceinline__ void ldsm_x4(uint32_t* r, uint32_t addr) {
    asm volatile("ldmatrix.sync.aligned.m8n8.x4.shared.b16 {%0,%1,%2,%3}, [%4];"
                 : "=r"(r[0]), "=r"(r[1]), "=r"(r[2]), "=r"(r[3]) : "r"(addr));
}
__device__ __forceinline__ void ldsm_x4_t(uint32_t* r, uint32_t addr) {
    asm volatile("ldmatrix.sync.aligned.m8n8.x4.trans.shared.b16 {%0,%1,%2,%3}, [%4];"
                 : "=r"(r[0]), "=r"(r[1]), "=r"(r[2]), "=r"(r[3]) : "r"(addr));
}
__device__ __forceinline__ void mma_bf16(float* d, const uint32_t* a, uint32_t b0, uint32_t b1) {
    asm volatile(
        "mma.sync.aligned.m16n8k16.row.col.f32.bf16.bf16.f32 "
        "{%0,%1,%2,%3}, {%4,%5,%6,%7}, {%8,%9}, {%0,%1,%2,%3};"
        : "+f"(d[0]), "+f"(d[1]), "+f"(d[2]), "+f"(d[3])
        : "r"(a[0]), "r"(a[1]), "r"(a[2]), "r"(a[3]), "r"(b0), "r"(b1));
}

// pack 4 floats -> 4 bf16 hi (uint2) and 4 bf16 lo (uint2)
__device__ __forceinline__ void split4(float4 v, uint2& uh, uint2& ul) {
    __nv_bfloat16 h0 = __float2bfloat16_rn(v.x);
    __nv_bfloat16 h1 = __float2bfloat16_rn(v.y);
    __nv_bfloat16 h2 = __float2bfloat16_rn(v.z);
    __nv_bfloat16 h3 = __float2bfloat16_rn(v.w);
    __nv_bfloat16 l0 = __float2bfloat16_rn(v.x - __bfloat162float(h0));
    __nv_bfloat16 l1 = __float2bfloat16_rn(v.y - __bfloat162float(h1));
    __nv_bfloat16 l2 = __float2bfloat16_rn(v.z - __bfloat162float(h2));
    __nv_bfloat16 l3 = __float2bfloat16_rn(v.w - __bfloat162float(h3));
    __nv_bfloat162 ph0; ph0.x = h0; ph0.y = h1;
    __nv_bfloat162 ph1; ph1.x = h2; ph1.y = h3;
    __nv_bfloat162 pl0; pl0.x = l0; pl0.y = l1;
    __nv_bfloat162 pl1; pl1.x = l2; pl1.y = l3;
    uh.x = *(uint32_t*)&ph0; uh.y = *(uint32_t*)&ph1;
    ul.x = *(uint32_t*)&pl0; ul.y = *(uint32_t*)&pl1;
}

// ---------------- routing ----------------------------------------------------
__global__ void reset_counts_k() { if (threadIdx.x < NE) g_cnt[threadIdx.x] = 0; }

__global__ void route_k(const int* __restrict__ idx) {
    int a = blockIdx.x * blockDim.x + threadIdx.x;
    if (a >= NA) return;
    int e = idx[a];
    int p = atomicAdd(&g_cnt[e], 1);
    g_tok[e * NA + p] = a >> 1;
    g_asg[e * NA + p] = a;
}

// ---------------- GEMM (split-bf16 3-term, mma.sync) -------------------------
// UP:  A = x (gathered), B phys cols 0-63 = w1[bx*64..], 64-127 = w2[bx*64..]
//      K = DM, epilogue: hidden = silu(gate)*value   (grid.x = 64)
// DOWN:A = g_hidden (gathered), B = w3 cols bx*128.., K = DF,
//      epilogue: obuf = acc * ew[a]                  (grid.x = 8)
template<bool UP>
__global__ void __launch_bounds__(256, 1) gemm_k(const float* __restrict__ xin,
                                                 const float* __restrict__ wa,
                                                 const float* __restrict__ wb,
                                                 const float* __restrict__ ew) {
    constexpr int KTOT = UP ? DM : DF;
    constexpr int NS   = KTOT / BK;
    const int e   = blockIdx.z;
    const int cnt = g_cnt[e];
    const int m0  = blockIdx.y * BM;
    if (m0 >= cnt) return;
    const int bx  = blockIdx.x;

    extern __shared__ char smem[];
    const uint32_t sbase = smem_u32(smem);
    const int tid  = threadIdx.x;
    const int lane = tid & 31;
    const int wid  = tid >> 5;
    const int wm   = wid & 1;        // 2 warp-rows (64 each)
    const int wn   = wid >> 1;       // 4 warp-cols (32 each)

    // ---- A gmem mapping: thread covers row tid/2, 16 consecutive k ----
    const int amr = tid >> 1;
    const int akc = (tid & 1) * 16;
    const float* arow = nullptr;
    {
        int m = m0 + amr;
        if (m < cnt) {
            int slot = UP ? g_tok[e * NA + m] : g_asg[e * NA + m];
            arow = (UP ? xin : g_hidden) + (size_t)slot * (UP ? DM : DF);
        }
    }

    // ---- B gmem mapping: thread covers k-row tid/8, 16 consecutive n ----
    const int bkr = tid >> 3;
    const int bnc = (tid & 7) * 16;      // physical col 0..112
    const float* bsrc;
    int ldb;
    if (UP) {
        ldb = DF;
        const float* w = (bnc < 64) ? wa : wb;
        bsrc = w + (size_t)e * DM * DF + (size_t)bx * 64 + (bnc & 63);
    } else {
        ldb = DM;
        bsrc = wb + (size_t)e * DF * DM + (size_t)bx * 128 + bnc;
    }

    float acc[4][4][4];
    #pragma unroll
    for (int i = 0; i < 4; i++)
        #pragma unroll
        for (int j = 0; j < 4; j++)
            #pragma unroll
            for (int k = 0; k < 4; k++) acc[i][j][k] = 0.f;

    // ldmatrix address components (constant per thread)
    const uint32_t a_lm_row = (uint32_t)(wm * 64 + (lane & 15));   // + mt*16
    const uint32_t a_lm_k   = (uint32_t)((lane >> 4) * 8);         // + ks*16
    const uint32_t b_lm_k   = (uint32_t)(((lane >> 3) & 1) * 8 + (lane & 7)); // + ks*16
    const uint32_t b_lm_n   = (uint32_t)((lane >> 4) * 8);         // + nof
    int nof[2];
    if (UP) { nof[0] = wn * 16; nof[1] = 64 + wn * 16; }
    else    { nof[0] = wn * 32; nof[1] = wn * 32 + 16; }

    float4 pa[4], pb[4];
    // prefetch stage 0
    {
        if (arow) {
            const float4* p = (const float4*)(arow + akc);
            pa[0] = p[0]; pa[1] = p[1]; pa[2] = p[2]; pa[3] = p[3];
        } else pa[0] = pa[1] = pa[2] = pa[3] = make_float4(0.f,0.f,0.f,0.f);
        const float* q = bsrc + (size_t)bkr * ldb;
        pb[0] = *(const float4*)(q);
        pb[1] = *(const float4*)(q + 4);
        pb[2] = *(const float4*)(q + 8);
        pb[3] = *(const float4*)(q + 12);
    }

    #pragma unroll 1
    for (int s = 0; s < NS; s++) {
        const int b = s & 1;
        char* stg  = smem + b * STAGE;
        char* sAh  = stg;
        char* sAl  = stg + ST_A;
        char* sBh  = stg + 2 * ST_A;
        char* sBl  = stg + 2 * ST_A + ST_B;

        // store stage s (convert fp32 -> bf16 hi/lo)
        #pragma unroll
        for (int i = 0; i < 4; i++) {
            uint2 uh, ul;
            split4(pa[i], uh, ul);
            uint32_t off = (uint32_t)(amr * (A_STRIDE * 2) + (akc + 4 * i) * 2);
            *(uint2*)(sAh + off) = uh;
            *(uint2*)(sAl + off) = ul;
        }
        #pragma unroll
        for (int i = 0; i < 4; i++) {
            uint2 uh, ul;
            split4(pb[i], uh, ul);
            uint32_t off = (uint32_t)(bkr * (B_STRIDE * 2) + (bnc + 4 * i) * 2);
            *(uint2*)(sBh + off) = uh;
            *(uint2*)(sBl + off) = ul;
        }
        __syncthreads();

        // prefetch stage s+1
        if (s + 1 < NS) {
            const int k0 = (s + 1) * BK;
            if (arow) {
                const float4* p = (const float4*)(arow + k0 + akc);
                pa[0] = p[0]; pa[1] = p[1]; pa[2] = p[2]; pa[3] = p[3];
            }
            const float* q = bsrc + (size_t)(k0 + bkr) * ldb;
            pb[0] = *(const float4*)(q);
            pb[1] = *(const float4*)(q + 4);
            pb[2] = *(const float4*)(q + 8);
            pb[3] = *(const float4*)(q + 12);
        }

        // compute stage s: two k16 sub-steps
        const uint32_t uAh = sbase + b * STAGE;
        const uint32_t uBh = uAh + 2 * ST_A;
        #pragma unroll
        for (int ks = 0; ks < 2; ks++) {
            uint32_t ah[4][4], al[4][4];
            #pragma unroll
            for (int mt = 0; mt < 4; mt++) {
                uint32_t addr = uAh + (a_lm_row + mt * 16) * (A_STRIDE * 2)
                              + (a_lm_k + ks * 16) * 2;
                ldsm_x4(ah[mt], addr);
                ldsm_x4(al[mt], addr + ST_A);
            }
            uint32_t bh[2][4], bl[2][4];
            #pragma unroll
            for (int g = 0; g < 2; g++) {
                uint32_t addr = uBh + (b_lm_k + ks * 16) * (B_STRIDE * 2)
                              + (nof[g] + b_lm_n) * 2;
                ldsm_x4_t(bh[g], addr);
                ldsm_x4_t(bl[g], addr + ST_B);
            }
            #pragma unroll
            for (int mt = 0; mt < 4; mt++)
                #pragma unroll
                for (int nt = 0; nt < 4; nt++) {
                    const int g = nt >> 1, j = (nt & 1) * 2;
                    mma_bf16(acc[mt][nt], ah[mt], bh[g][j], bh[g][j + 1]);
                    mma_bf16(acc[mt][nt], al[mt], bh[g][j], bh[g][j + 1]);
                    mma_bf16(acc[mt][nt], ah[mt], bl[g][j], bl[g][j + 1]);
                }
        }
        __syncthreads();
    }

    // ---- epilogue ----
    const int qrow = lane >> 2;
    const int qcol = (lane & 3) * 2;
    #pragma unroll
    for (int mt = 0; mt < 4; mt++) {
        #pragma unroll
        for (int h = 0; h < 2; h++) {
            int m = m0 + wm * 64 + mt * 16 + qrow + 8 * h;
            if (m >= cnt) continue;
            int a = g_asg[e * NA + m];
            if (UP) {
                float* hrow = g_hidden + (size_t)a * DF + bx * 64 + wn * 16;
                #pragma unroll
                for (int nt = 0; nt < 2; nt++) {
                    float g0 = acc[mt][nt][h * 2], g1 = acc[mt][nt][h * 2 + 1];
                    float v0 = acc[mt][nt + 2][h * 2], v1 = acc[mt][nt + 2][h * 2 + 1];
                    float2 r;
                    r.x = v0 * g0 / (1.f + expf(-g0));
                    r.y = v1 * g1 / (1.f + expf(-g1));
                    *(float2*)(hrow + nt * 8 + qcol) = r;
                }
            } else {
                float sc = ew[a];
                float* orow = g_obuf + (size_t)a * DM + bx * 128 + wn * 32;
                #pragma unroll
                for (int nt = 0; nt < 4; nt++) {
                    float2 r;
                    r.x = acc[mt][nt][h * 2] * sc;
                    r.y = acc[mt][nt][h * 2 + 1] * sc;
                    *(float2*)(orow + nt * 8 + qcol) = r;
                }
            }
        }
    }
}

// ---------------- combine -----------------------------------------------------
__global__ void combine_k(float* __restrict__ out) {
    int i = blockIdx.x * blockDim.x + threadIdx.x;
    const int W = DM / 4;
    if (i >= NT * W) return;
    int t = i / W;
    int c = i - t * W;
    const float4* buf = (const float4*)g_obuf;
    float4 a0 = buf[(size_t)(2 * t) * W + c];
    float4 a1 = buf[(size_t)(2 * t + 1) * W + c];
    ((float4*)out)[i] = make_float4(a0.x + a1.x, a0.y + a1.y, a0.z + a1.z, a0.w + a1.w);
}

// ---------------- launch ------------------------------------------------------
extern "C" void kernel_launch(void* const* d_in, const int* in_sizes, int n_in,
                              void* d_out, int out_size) {
    const float* x   = (const float*)d_in[0];
    const int*   idx = (const int*)d_in[1];
    const float* ew  = (const float*)d_in[2];
    const float* w1  = (const float*)d_in[3];
    const float* w2  = (const float*)d_in[4];
    const float* w3  = (const float*)d_in[5];
    float* out = (float*)d_out;

    cudaFuncSetAttribute(gemm_k<true>,  cudaFuncAttributeMaxDynamicSharedMemorySize, SMEMSZ);
    cudaFuncSetAttribute(gemm_k<false>, cudaFuncAttributeMaxDynamicSharedMemorySize, SMEMSZ);

    reset_counts_k<<<1, 32>>>();
    route_k<<<NA / 256, 256>>>(idx);

    // up: 64 n-tiles (w1|w2 64-col halves), 32 m-tiles, 8 experts
    gemm_k<true><<<dim3(64, NA / BM, NE), 256, SMEMSZ>>>(x, w1, w2, ew);
    // down: 8 n-tiles of 128, 32 m-tiles, 8 experts
    gemm_k<false><<<dim3(8, NA / BM, NE), 256, SMEMSZ>>>(nullptr, nullptr, w3, ew);

    combine_k<<<(NT * (DM / 4) + 255) / 256, 256>>>(out);
}